// round 8
// baseline (speedup 1.0000x reference)
#include <cuda_runtime.h>
#include <cuda_fp16.h>
#include <cstdint>

// ---------------- problem constants ----------------
#define K_CODES   1024
#define D_DIM     128
#define N_TOK     65536        // 64 * 32 * 32 tokens (BHWC order)
#define Z_ELEMS   8388608      // 64 * 128 * 32 * 32
#define EMA       0.99f
#define EPSV      1e-5f
#define EPS_FLAG  0.15f        // screen1 gap threshold (fp16 single pass)
#define EPS2      2e-3f        // screen2 gap threshold (fp16 hi/lo 3-pass)

// ---------------- output layout (flattened reference tuple, fp32) ----------------
#define Q_OFF     0
#define IDX_OFF   8388608
#define L_OFF     8454144
#define CB_OFF    8454146
#define CNT_OFF   8585218
#define EMW_OFF   8586242

// ---------------- smem layout for argmin/screen1 (bytes) ----------------
#define SM_A      0            // 32KB: A fp16 frag-packed
#define SM_B      32768        // 2 stages * 16KB
#define SM_CN     65536        // 1024 floats
#define SM_REDV   69632
#define SM_REDI   70656
#define SM_RED2   71680
#define SM_TOTAL  72704

// ---------------- smem layout for screen2 (bytes) ----------------
#define S2_ZT     0            // 128 tokens x 132 floats = 67584
#define S2_AH     67584        // 2048 uint4 = 32768
#define S2_AL     100352       // 32768
#define S2_B      133120       // 2 stages * (16KB hi + 16KB lo) = 65536
#define S2_CN     198656       // 4096
#define S2_REDV   202752       // 1024
#define S2_REDI   203776       // 1024
#define S2_RED2   204800       // 1024
#define S2_TOTAL  205824

// ---------------- global scratch ----------------
__device__ uint4    g_Ah[512 * 2048];     // z fp16, frag-packed (16.7MB)
__device__ uint32_t g_Bh[65536];          // cb fp16 hi frags (256KB)
__device__ uint32_t g_Bl[65536];          // cb fp16 lo frags (256KB)
__device__ float    g_cnorm[K_CODES];
__device__ float    g_counts[K_CODES];
__device__ float    g_dw[K_CODES * D_DIM];
__device__ int      g_idx[N_TOK];
__device__ float    g_loss;
__device__ float    g_weights[K_CODES];
__device__ int      g_fixcnt;
__device__ int      g_fixlist[N_TOK];
__device__ int      g_fixcnt2;
__device__ int      g_fixlist2[N_TOK];

// ---------------- helpers ----------------
__device__ __forceinline__ uint32_t smem_u32(const void* p) {
    uint32_t a;
    asm("{ .reg .u64 t; cvta.to.shared.u64 t, %1; cvt.u32.u64 %0, t; }" : "=r"(a) : "l"(p));
    return a;
}
__device__ __forceinline__ uint32_t packh(float a, float b) {
    __half2 t = __floats2half2_rn(a, b);
    return *(uint32_t*)&t;
}
__device__ __forceinline__ void mma16(float* c, const uint32_t* a, const uint32_t* b) {
    asm volatile("mma.sync.aligned.m16n8k16.row.col.f32.f16.f16.f32 "
                 "{%0,%1,%2,%3}, {%4,%5,%6,%7}, {%8,%9}, {%0,%1,%2,%3};"
                 : "+f"(c[0]), "+f"(c[1]), "+f"(c[2]), "+f"(c[3])
                 : "r"(a[0]), "r"(a[1]), "r"(a[2]), "r"(a[3]), "r"(b[0]), "r"(b[1]));
}
__device__ __forceinline__ void merge3(float& b1, int& i1, float& b2, float v, int id) {
    if (v < b1 || (v == b1 && id < i1)) { b2 = b1; b1 = v; i1 = id; }
    else if (v < b2) b2 = v;
}
#define CP16(dst, src) \
    asm volatile("cp.async.cg.shared.global [%0], [%1], 16;" :: "r"(dst), "l"(src) : "memory")
#define CP_COMMIT() asm volatile("cp.async.commit_group;" ::: "memory")
#define CP_WAIT1()  asm volatile("cp.async.wait_group 1;" ::: "memory")
#define CP_WAIT0()  asm volatile("cp.async.wait_group 0;" ::: "memory")

// ---------------- fused prep: zero + cnorm + fp16 hi/lo cb fragments ----------------
__global__ void __launch_bounds__(128) prep_all_kernel(const float* __restrict__ cb) {
    const int k = blockIdx.x, d = threadIdx.x;
    float v = cb[k * D_DIM + d];

    g_dw[k * D_DIM + d] = 0.f;
    if (d == 0) g_counts[k] = 0.f;
    if (k == 0 && d == 0) { g_loss = 0.f; g_fixcnt = 0; g_fixcnt2 = 0; }

    float vn = __shfl_xor_sync(0xffffffffu, v, 1);

    float sq = v * v;
    #pragma unroll
    for (int o = 16; o; o >>= 1) sq += __shfl_xor_sync(0xffffffffu, sq, o);
    __shared__ float ws[4];
    if ((d & 31) == 0) ws[d >> 5] = sq;
    __syncthreads();
    if (d == 0) g_cnorm[k] = ws[0] + ws[1] + ws[2] + ws[3];

    if ((d & 1) == 0) {
        float h0 = __half2float(__float2half_rn(v));
        float h1 = __half2float(__float2half_rn(vn));
        uint32_t ph = packh(h0, h1);
        uint32_t pl = packh(v - h0, vn - h1);
        int tile = k >> 6, c = k & 63;
        int nf = c >> 3, np = nf >> 1, nin = c & 7;
        int s  = d >> 4, dk = d & 15;
        int kb = dk >> 3, lq = (dk & 7) >> 1;
        int lane = nin * 4 + lq;
        int comp = (nf & 1) * 2 + kb;
        int idx = (((tile * 8 + s) * 4 + np) * 32 + lane) * 4 + comp;
        g_Bh[idx] = ph;
        g_Bl[idx] = pl;
    }
}

// ---------------- z -> fp16, mma-fragment-packed ----------------
#define ZT_STRIDE 132
__global__ void __launch_bounds__(256) prep_z_kernel(const float* __restrict__ z) {
    extern __shared__ float zt[];                     // [128 d][ZT_STRIDE]
    const int tid  = threadIdx.x;
    const int ctaM = blockIdx.x;
    const int b  = ctaM >> 3;
    const int s0 = (ctaM & 7) << 7;
    const float* zp = z + (size_t)b * 131072 + s0;

    #pragma unroll
    for (int j = 0; j < 16; j++) {
        int u  = j * 256 + tid;
        int d  = u >> 5, t4 = (u & 31) << 2;
        float4 v = *(const float4*)&zp[(size_t)d * 1024 + t4];
        *(float4*)&zt[d * ZT_STRIDE + t4] = v;
    }
    __syncthreads();

    #pragma unroll
    for (int j = 0; j < 8; j++) {
        int u = j * 256 + tid;
        int f = u >> 8, s = (u >> 5) & 7, l = u & 31;
        int T0 = f * 16 + (l >> 2);
        int c0 = s * 16 + (l & 3) * 2;
        uint32_t rh[4];
        rh[0] = packh(zt[(c0    ) * ZT_STRIDE + T0],     zt[(c0 + 1) * ZT_STRIDE + T0]);
        rh[1] = packh(zt[(c0    ) * ZT_STRIDE + T0 + 8], zt[(c0 + 1) * ZT_STRIDE + T0 + 8]);
        rh[2] = packh(zt[(c0 + 8) * ZT_STRIDE + T0],     zt[(c0 + 9) * ZT_STRIDE + T0]);
        rh[3] = packh(zt[(c0 + 8) * ZT_STRIDE + T0 + 8], zt[(c0 + 9) * ZT_STRIDE + T0 + 8]);
        g_Ah[ctaM * 2048 + u] = make_uint4(rh[0], rh[1], rh[2], rh[3]);
    }
}

// ---------------- screen1: fp16 GEMM + argmin (best + 2nd best) ----------------
__global__ void __launch_bounds__(256, 2) argmin_mma_kernel() {
    extern __shared__ char smem[];
    const uint32_t smb = smem_u32(smem);
    const int tid = threadIdx.x;
    const int l   = tid & 31, w = tid >> 5;
    const int wr  = w & 3,    wc = w >> 2;
    const int lq  = l & 3,    lr = l >> 2;
    const int ctaM = blockIdx.x;

    {
        const uint4* gAh = g_Ah + (size_t)ctaM * 2048;
        #pragma unroll
        for (int j = 0; j < 8; j++) {
            int c = j * 256 + tid;
            CP16(smb + SM_A + c * 16, gAh + c);
        }
        CP16(smb + SM_CN + tid * 16, g_cnorm + tid * 4);
        CP_COMMIT();
    }
    {
        const uint4* bh = (const uint4*)g_Bh;
        #pragma unroll
        for (int j = 0; j < 4; j++) {
            int c = j * 256 + tid;
            CP16(smb + SM_B + c * 16, bh + c);
        }
        CP_COMMIT();
    }

    float acc[2][4][4];
    float best [2][2] = {{3.4e38f, 3.4e38f}, {3.4e38f, 3.4e38f}};
    float best2[2][2] = {{3.4e38f, 3.4e38f}, {3.4e38f, 3.4e38f}};
    int   bidx [2][2] = {{0, 0}, {0, 0}};

    for (int t = 0; t < 16; t++) {
        if (t < 15) {
            const uint4* bh = (const uint4*)g_Bh + (t + 1) * 1024;
            uint32_t dst = smb + SM_B + ((t + 1) & 1) * 16384;
            #pragma unroll
            for (int j = 0; j < 4; j++) {
                int c = j * 256 + tid;
                CP16(dst + c * 16, bh + c);
            }
            CP_COMMIT();
            CP_WAIT1();
        } else {
            CP_WAIT0();
        }
        __syncthreads();

        #pragma unroll
        for (int m = 0; m < 2; m++)
            #pragma unroll
            for (int n = 0; n < 4; n++)
                #pragma unroll
                for (int e = 0; e < 4; e++) acc[m][n][e] = 0.f;

        const uint4* Ah4 = (const uint4*)(smem + SM_A);
        const uint4* Bh4 = (const uint4*)(smem + SM_B + (size_t)(t & 1) * 16384);

        #pragma unroll
        for (int s = 0; s < 8; s++) {
            uint4 A0 = Ah4[((wr * 2 + 0) * 8 + s) * 32 + l];
            uint4 A1 = Ah4[((wr * 2 + 1) * 8 + s) * 32 + l];
            uint4 B0 = Bh4[(s * 4 + wc * 2 + 0) * 32 + l];
            uint4 B1 = Bh4[(s * 4 + wc * 2 + 1) * 32 + l];

            uint32_t ah[2][4] = {{A0.x, A0.y, A0.z, A0.w}, {A1.x, A1.y, A1.z, A1.w}};
            uint32_t bh[4][2] = {{B0.x, B0.y}, {B0.z, B0.w}, {B1.x, B1.y}, {B1.z, B1.w}};

            #pragma unroll
            for (int m = 0; m < 2; m++)
                #pragma unroll
                for (int n = 0; n < 4; n++) mma16(acc[m][n], ah[m], bh[n]);
        }

        const float* cn = (const float*)(smem + SM_CN);
        #pragma unroll
        for (int m = 0; m < 2; m++)
            #pragma unroll
            for (int n = 0; n < 4; n++)
                #pragma unroll
                for (int e = 0; e < 4; e++) {
                    int code = t * 64 + (wc * 4 + n) * 8 + lq * 2 + (e & 1);
                    float dist = fmaf(-2.f, acc[m][n][e], cn[code]);
                    int rb = e >> 1;
                    merge3(best[m][rb], bidx[m][rb], best2[m][rb], dist, code);
                }
        __syncthreads();
    }

    float* redv = (float*)(smem + SM_REDV);
    int*   redi = (int*)(smem + SM_REDI);
    float* red2 = (float*)(smem + SM_RED2);
    #pragma unroll
    for (int m = 0; m < 2; m++)
        #pragma unroll
        for (int rb = 0; rb < 2; rb++) {
            float v1 = best[m][rb], v2 = best2[m][rb];
            int   id = bidx[m][rb];
            #pragma unroll
            for (int off = 1; off <= 2; off <<= 1) {
                float ov1 = __shfl_xor_sync(0xffffffffu, v1, off);
                float ov2 = __shfl_xor_sync(0xffffffffu, v2, off);
                int   oi  = __shfl_xor_sync(0xffffffffu, id, off);
                merge3(v1, id, v2, ov1, oi);
                merge3(v1, id, v2, ov2, 0x7fffffff);
            }
            if (lq == 0) {
                int row = wr * 32 + m * 16 + rb * 8 + lr;
                redv[wc * 128 + row] = v1;
                redi[wc * 128 + row] = id;
                red2[wc * 128 + row] = v2;
            }
        }
    __syncthreads();
    if (tid < 128) {
        float v1 = redv[tid],       s1 = red2[tid];
        float w1 = redv[128 + tid], w2 = red2[128 + tid];
        int   i1 = redi[tid],       j1 = redi[128 + tid];
        merge3(v1, i1, s1, w1, j1);
        merge3(v1, i1, s1, w2, 0x7fffffff);
        int token = ctaM * 128 + tid;
        g_idx[token] = i1;
        if (s1 - v1 < EPS_FLAG) {
            int p = atomicAdd(&g_fixcnt, 1);
            g_fixlist[p] = token;
        }
    }
}

// ---------------- screen2: fp16 hi/lo 3-pass on flagged tokens ----------------
__global__ void __launch_bounds__(256) screen2_kernel(const float* __restrict__ z) {
    extern __shared__ char smem[];
    const uint32_t smb = smem_u32(smem);
    float* zt = (float*)(smem + S2_ZT);               // [128 tok][132]
    uint4* Ah = (uint4*)(smem + S2_AH);
    uint4* Al = (uint4*)(smem + S2_AL);
    const int tid = threadIdx.x;
    const int l   = tid & 31, w = tid >> 5;
    const int wr  = w & 3,    wc = w >> 2;
    const int lq  = l & 3,    lr = l >> 2;

    const int cnt = g_fixcnt;
    const int nb = (cnt + 127) >> 7;

    for (int batch = blockIdx.x; batch < nb; batch += gridDim.x) {
        for (int i = tid; i < K_CODES; i += 256)
            ((float*)(smem + S2_CN))[i] = g_cnorm[i];

        // gather: 2 threads per token, 64 d each (strided LDG, L2-resident z)
        {
            int t = tid >> 1, half = tid & 1;
            int ti = batch * 128 + t;
            int token = g_fixlist[ti < cnt ? ti : 0];
            int b = token >> 10, s = token & 1023;
            const float* zp = z + (size_t)b * 131072 + s + (size_t)(half * 64) * 1024;
            float* row = zt + t * 132 + half * 64;
            #pragma unroll 8
            for (int dd = 0; dd < 64; dd++) row[dd] = zp[(size_t)dd * 1024];
        }
        __syncthreads();

        // frag pack hi/lo
        #pragma unroll
        for (int j = 0; j < 8; j++) {
            int u = j * 256 + tid;
            int f = u >> 8, s = (u >> 5) & 7, li = u & 31;
            int T0 = f * 16 + (li >> 2);
            int c0 = s * 16 + (li & 3) * 2;
            float v[4][2];
            v[0][0] = zt[T0 * 132 + c0];           v[0][1] = zt[T0 * 132 + c0 + 1];
            v[1][0] = zt[(T0 + 8) * 132 + c0];     v[1][1] = zt[(T0 + 8) * 132 + c0 + 1];
            v[2][0] = zt[T0 * 132 + c0 + 8];       v[2][1] = zt[T0 * 132 + c0 + 9];
            v[3][0] = zt[(T0 + 8) * 132 + c0 + 8]; v[3][1] = zt[(T0 + 8) * 132 + c0 + 9];
            uint32_t rh[4], rl[4];
            #pragma unroll
            for (int r = 0; r < 4; r++) {
                float h0 = __half2float(__float2half_rn(v[r][0]));
                float h1 = __half2float(__float2half_rn(v[r][1]));
                rh[r] = packh(h0, h1);
                rl[r] = packh(v[r][0] - h0, v[r][1] - h1);
            }
            Ah[u] = make_uint4(rh[0], rh[1], rh[2], rh[3]);
            Al[u] = make_uint4(rl[0], rl[1], rl[2], rl[3]);
        }

        // preload B tile 0 (hi+lo)
        {
            const uint4* bh = (const uint4*)g_Bh;
            const uint4* bl = (const uint4*)g_Bl;
            #pragma unroll
            for (int j = 0; j < 4; j++) {
                int c = j * 256 + tid;
                CP16(smb + S2_B + c * 16, bh + c);
                CP16(smb + S2_B + 16384 + c * 16, bl + c);
            }
            CP_COMMIT();
        }
        __syncthreads();

        float acc[2][4][4];
        float best [2][2] = {{3.4e38f, 3.4e38f}, {3.4e38f, 3.4e38f}};
        float best2[2][2] = {{3.4e38f, 3.4e38f}, {3.4e38f, 3.4e38f}};
        int   bidx [2][2] = {{0, 0}, {0, 0}};

        for (int t = 0; t < 16; t++) {
            if (t < 15) {
                const uint4* bh = (const uint4*)g_Bh + (t + 1) * 1024;
                const uint4* bl = (const uint4*)g_Bl + (t + 1) * 1024;
                uint32_t dst = smb + S2_B + ((t + 1) & 1) * 32768;
                #pragma unroll
                for (int j = 0; j < 4; j++) {
                    int c = j * 256 + tid;
                    CP16(dst + c * 16, bh + c);
                    CP16(dst + 16384 + c * 16, bl + c);
                }
                CP_COMMIT();
                CP_WAIT1();
            } else {
                CP_WAIT0();
            }
            __syncthreads();

            #pragma unroll
            for (int m = 0; m < 2; m++)
                #pragma unroll
                for (int n = 0; n < 4; n++)
                    #pragma unroll
                    for (int e = 0; e < 4; e++) acc[m][n][e] = 0.f;

            const uint4* Bh4 = (const uint4*)(smem + S2_B + (size_t)(t & 1) * 32768);
            const uint4* Bl4 = (const uint4*)(smem + S2_B + (size_t)(t & 1) * 32768 + 16384);

            #pragma unroll
            for (int s = 0; s < 8; s++) {
                uint4 A0h = Ah[((wr * 2 + 0) * 8 + s) * 32 + l];
                uint4 A1h = Ah[((wr * 2 + 1) * 8 + s) * 32 + l];
                uint4 A0l = Al[((wr * 2 + 0) * 8 + s) * 32 + l];
                uint4 A1l = Al[((wr * 2 + 1) * 8 + s) * 32 + l];
                uint4 B0h = Bh4[(s * 4 + wc * 2 + 0) * 32 + l];
                uint4 B1h = Bh4[(s * 4 + wc * 2 + 1) * 32 + l];
                uint4 B0l = Bl4[(s * 4 + wc * 2 + 0) * 32 + l];
                uint4 B1l = Bl4[(s * 4 + wc * 2 + 1) * 32 + l];

                uint32_t ah[2][4] = {{A0h.x, A0h.y, A0h.z, A0h.w}, {A1h.x, A1h.y, A1h.z, A1h.w}};
                uint32_t al[2][4] = {{A0l.x, A0l.y, A0l.z, A0l.w}, {A1l.x, A1l.y, A1l.z, A1l.w}};
                uint32_t bh[4][2] = {{B0h.x, B0h.y}, {B0h.z, B0h.w}, {B1h.x, B1h.y}, {B1h.z, B1h.w}};
                uint32_t bl[4][2] = {{B0l.x, B0l.y}, {B0l.z, B0l.w}, {B1l.x, B1l.y}, {B1l.z, B1l.w}};

                #pragma unroll
                for (int m = 0; m < 2; m++)
                    #pragma unroll
                    for (int n = 0; n < 4; n++) mma16(acc[m][n], ah[m], bh[n]);
                #pragma unroll
                for (int m = 0; m < 2; m++)
                    #pragma unroll
                    for (int n = 0; n < 4; n++) mma16(acc[m][n], ah[m], bl[n]);
                #pragma unroll
                for (int m = 0; m < 2; m++)
                    #pragma unroll
                    for (int n = 0; n < 4; n++) mma16(acc[m][n], al[m], bh[n]);
            }

            const float* cn = (const float*)(smem + S2_CN);
            #pragma unroll
            for (int m = 0; m < 2; m++)
                #pragma unroll
                for (int n = 0; n < 4; n++)
                    #pragma unroll
                    for (int e = 0; e < 4; e++) {
                        int code = t * 64 + (wc * 4 + n) * 8 + lq * 2 + (e & 1);
                        float dist = fmaf(-2.f, acc[m][n][e], cn[code]);
                        int rb = e >> 1;
                        merge3(best[m][rb], bidx[m][rb], best2[m][rb], dist, code);
                    }
            __syncthreads();
        }

        float* redv = (float*)(smem + S2_REDV);
        int*   redi = (int*)(smem + S2_REDI);
        float* red2 = (float*)(smem + S2_RED2);
        #pragma unroll
        for (int m = 0; m < 2; m++)
            #pragma unroll
            for (int rb = 0; rb < 2; rb++) {
                float v1 = best[m][rb], v2 = best2[m][rb];
                int   id = bidx[m][rb];
                #pragma unroll
                for (int off = 1; off <= 2; off <<= 1) {
                    float ov1 = __shfl_xor_sync(0xffffffffu, v1, off);
                    float ov2 = __shfl_xor_sync(0xffffffffu, v2, off);
                    int   oi  = __shfl_xor_sync(0xffffffffu, id, off);
                    merge3(v1, id, v2, ov1, oi);
                    merge3(v1, id, v2, ov2, 0x7fffffff);
                }
                if (lq == 0) {
                    int row = wr * 32 + m * 16 + rb * 8 + lr;
                    redv[wc * 128 + row] = v1;
                    redi[wc * 128 + row] = id;
                    red2[wc * 128 + row] = v2;
                }
            }
        __syncthreads();
        if (tid < 128) {
            int ti = batch * 128 + tid;
            if (ti < cnt) {
                float v1 = redv[tid],       s1 = red2[tid];
                float w1 = redv[128 + tid], w2 = red2[128 + tid];
                int   i1 = redi[tid],       j1 = redi[128 + tid];
                merge3(v1, i1, s1, w1, j1);
                merge3(v1, i1, s1, w2, 0x7fffffff);
                int token = g_fixlist[ti];
                g_idx[token] = i1;
                if (s1 - v1 < EPS2) {
                    int p = atomicAdd(&g_fixcnt2, 1);
                    g_fixlist2[p] = token;
                }
            }
        }
        __syncthreads();
    }
}

// ---------------- exact fp32 recompute for screen2 near-ties (tiny) ----------------
#define FIX_G 16
#define CB_STR 132
__global__ void __launch_bounds__(256) fixup_kernel(const float* __restrict__ z,
                                                    const float* __restrict__ cb) {
    __shared__ float ztok[FIX_G][D_DIM];
    __shared__ float cbt[64 * CB_STR];
    __shared__ float cnt_[64];
    const int tid = threadIdx.x;
    const int tk = tid >> 4, cs = tid & 15;
    int cnt = g_fixcnt2;
    int nIter = (cnt + FIX_G - 1) / FIX_G;

    for (int it = blockIdx.x; it < nIter; it += gridDim.x) {
        int base = it * FIX_G;
        for (int u = tid; u < FIX_G * D_DIM; u += 256) {
            int tt = u >> 7, d = u & 127;
            float v = 0.f;
            int ti = base + tt;
            if (ti < cnt) {
                int token = g_fixlist2[ti];
                int b = token >> 10, s = token & 1023;
                v = z[(size_t)b * 131072 + (size_t)d * 1024 + s];
            }
            ztok[tt][d] = v;
        }

        float bv = 3.4e38f;
        int   bi = 0;
        for (int tile = 0; tile < 16; tile++) {
            __syncthreads();
            for (int u = tid; u < 2048; u += 256) {
                float4 vv = ((const float4*)cb)[tile * 2048 + u];
                *(float4*)&cbt[(u >> 5) * CB_STR + (u & 31) * 4] = vv;
            }
            if (tid < 64) cnt_[tid] = g_cnorm[tile * 64 + tid];
            __syncthreads();

            float dot[4] = {0.f, 0.f, 0.f, 0.f};
            const float* zp = ztok[tk];
            #pragma unroll 4
            for (int q = 0; q < D_DIM; q++) {
                float zv = zp[q];
                #pragma unroll
                for (int j = 0; j < 4; j++)
                    dot[j] = fmaf(zv, cbt[(cs + j * 16) * CB_STR + q], dot[j]);
            }
            #pragma unroll
            for (int j = 0; j < 4; j++) {
                int c = cs + j * 16;
                float dist = fmaf(-2.f, dot[j], cnt_[c]);
                int code = tile * 64 + c;
                if (dist < bv || (dist == bv && code < bi)) { bv = dist; bi = code; }
            }
        }
        #pragma unroll
        for (int off = 1; off < 16; off <<= 1) {
            float ov = __shfl_xor_sync(0xffffffffu, bv, off);
            int   oi = __shfl_xor_sync(0xffffffffu, bi, off);
            if (ov < bv || (ov == bv && oi < bi)) { bv = ov; bi = oi; }
        }
        if (cs == 0 && base + tk < cnt) g_idx[g_fixlist2[base + tk]] = bi;
        __syncthreads();
    }
}

// ---------------- gather quantized + loss + counts + idx (2 tokens/warp) ----------------
__global__ void __launch_bounds__(256) quant_kernel(const float* __restrict__ z,
                                                    const float* __restrict__ cb,
                                                    float* __restrict__ out) {
    int wid  = threadIdx.x >> 5;
    int lane = threadIdx.x & 31;
    int n0   = blockIdx.x * 16 + wid * 2;

    int k0 = g_idx[n0];
    int k1 = g_idx[n0 + 1];

    float4 q0 = *(const float4*)&cb[k0 * D_DIM + lane * 4];
    float4 q1 = *(const float4*)&cb[k1 * D_DIM + lane * 4];
    size_t o0 = (size_t)n0 * D_DIM + lane * 4;
    float4 z0 = *(const float4*)&z[o0];
    float4 z1 = *(const float4*)&z[o0 + D_DIM];
    *(float4*)&out[Q_OFF + o0]         = q0;
    *(float4*)&out[Q_OFF + o0 + D_DIM] = q1;

    float dx = q0.x - z0.x, dy = q0.y - z0.y, dz = q0.z - z0.z, dw = q0.w - z0.w;
    float s  = dx * dx + dy * dy + dz * dz + dw * dw;
    dx = q1.x - z1.x; dy = q1.y - z1.y; dz = q1.z - z1.z; dw = q1.w - z1.w;
    s += dx * dx + dy * dy + dz * dz + dw * dw;
    #pragma unroll
    for (int o = 16; o; o >>= 1) s += __shfl_xor_sync(0xffffffffu, s, o);

    __shared__ float ws[8];
    if (lane == 0) {
        ws[wid] = s;
        atomicAdd(&g_counts[k0], 1.f);
        atomicAdd(&g_counts[k1], 1.f);
        out[IDX_OFF + n0]     = (float)k0;
        out[IDX_OFF + n0 + 1] = (float)k1;
    }
    __syncthreads();
    if (threadIdx.x == 0) {
        float t = 0.f;
        #pragma unroll
        for (int i = 0; i < 8; i++) t += ws[i];
        atomicAdd(&g_loss, t);
    }
}

// ---------------- dw scatter: vector red.v4 (4 d per thread) ----------------
__global__ void __launch_bounds__(256) dw_kernel(const float* __restrict__ z) {
    int u  = blockIdx.x * blockDim.x + threadIdx.x;   // < 2097152
    int s  = u & 1023;
    int dg = (u >> 10) & 31;
    int b  = u >> 15;
    int n  = (b << 10) + s;
    int k  = g_idx[n];
    const float* zp = z + (size_t)b * 131072 + (size_t)dg * 4096 + s;
    float v0 = zp[0], v1 = zp[1024], v2 = zp[2048], v3 = zp[3072];
    float* dst = &g_dw[k * D_DIM + dg * 4];
    asm volatile("red.global.add.v4.f32 [%0], {%1,%2,%3,%4};"
                 :: "l"(dst), "f"(v0), "f"(v1), "f"(v2), "f"(v3) : "memory");
}

// ---------------- EMA count update + weights + losses ----------------
__global__ void finalize1_kernel(const float* __restrict__ ema_count,
                                 float* __restrict__ out) {
    int k = threadIdx.x;
    float c = EMA * ema_count[k] + (1.f - EMA) * g_counts[k];
    out[CNT_OFF + k] = c;

    __shared__ float sm[1024];
    sm[k] = c;
    __syncthreads();
    for (int o = 512; o; o >>= 1) {
        if (k < o) sm[k] += sm[k + o];
        __syncthreads();
    }
    float n = sm[0];
    g_weights[k] = (c + EPSV) / (n + K_CODES * EPSV) * n;

    if (k == 0) {
        float L = g_loss / 8388608.f;
        out[L_OFF]     = L;
        out[L_OFF + 1] = L;
    }
}

// ---------------- EMA weight update + new codebook ----------------
__global__ void finalize2_kernel(const float* __restrict__ ema_weight,
                                 float* __restrict__ out) {
    int i = blockIdx.x * blockDim.x + threadIdx.x;
    int k = i >> 7;
    float w = EMA * ema_weight[i] + (1.f - EMA) * g_dw[i];
    out[EMW_OFF + i] = w;
    out[CB_OFF + i]  = w / g_weights[k];
}

// ---------------- launch ----------------
extern "C" void kernel_launch(void* const* d_in, const int* in_sizes, int n_in,
                              void* d_out, int out_size) {
    const float* z          = (const float*)d_in[0];
    const float* cb         = (const float*)d_in[1];
    const float* ema_count  = (const float*)d_in[2];
    const float* ema_weight = (const float*)d_in[3];
    float* out = (float*)d_out;

    cudaFuncSetAttribute(argmin_mma_kernel,
                         cudaFuncAttributeMaxDynamicSharedMemorySize, SM_TOTAL);
    cudaFuncSetAttribute(prep_z_kernel,
                         cudaFuncAttributeMaxDynamicSharedMemorySize, 128 * ZT_STRIDE * 4);
    cudaFuncSetAttribute(screen2_kernel,
                         cudaFuncAttributeMaxDynamicSharedMemorySize, S2_TOTAL);

    prep_all_kernel<<<K_CODES, 128>>>(cb);
    prep_z_kernel<<<N_TOK / 128, 256, 128 * ZT_STRIDE * 4>>>(z);
    argmin_mma_kernel<<<N_TOK / 128, 256, SM_TOTAL>>>();
    screen2_kernel<<<64, 256, S2_TOTAL>>>(z);
    fixup_kernel<<<64, 256>>>(z, cb);
    quant_kernel<<<N_TOK / 16, 256>>>(z, cb, out);
    dw_kernel<<<Z_ELEMS / 1024, 256>>>(z);
    finalize1_kernel<<<1, 1024>>>(ema_count, out);
    finalize2_kernel<<<512, 256>>>(ema_weight, out);
}

// round 9
// speedup vs baseline: 1.4000x; 1.4000x over previous
#include <cuda_runtime.h>
#include <cuda_fp16.h>
#include <cstdint>

// ---------------- problem constants ----------------
#define K_CODES   1024
#define D_DIM     128
#define N_TOK     65536        // 64 * 32 * 32 tokens (BHWC order)
#define Z_ELEMS   8388608      // 64 * 128 * 32 * 32
#define EMA       0.99f
#define EPSV      1e-5f
#define EPS_FLAG  0.15f        // approx-gap threshold for exact recompute (7.8 sigma)

// ---------------- output layout (flattened reference tuple, fp32) ----------------
#define Q_OFF     0
#define IDX_OFF   8388608
#define L_OFF     8454144
#define CB_OFF    8454146
#define CNT_OFF   8585218
#define EMW_OFF   8586242

// ---------------- smem layout for argmin (bytes) ----------------
#define SM_A      0            // 32KB: A fp16 frag-packed
#define SM_B      32768        // 2 stages * 16KB
#define SM_CN     65536        // 1024 floats
#define SM_REDV   69632        // 256 floats (best)
#define SM_REDI   70656        // 256 ints  (best idx)
#define SM_RED2   71680        // 256 floats (second best)
#define SM_TOTAL  72704

// ---------------- global scratch ----------------
__device__ uint4    g_Ah[512 * 2048];     // z fp16, frag-packed [cta][f8][s8][lane32] (16.7MB)
__device__ uint32_t g_Bh[65536];          // cb fp16 [tile16][s8][np4][lane32][comp4] (256KB)
__device__ float    g_cnorm[K_CODES];
__device__ float    g_counts[K_CODES];
__device__ float    g_dw[K_CODES * D_DIM];
__device__ int      g_idx[N_TOK];
__device__ float    g_loss;
__device__ float    g_weights[K_CODES];
__device__ int      g_fixcnt;
__device__ int      g_fixlist[N_TOK];

// ---------------- helpers ----------------
__device__ __forceinline__ uint32_t smem_u32(const void* p) {
    uint32_t a;
    asm("{ .reg .u64 t; cvta.to.shared.u64 t, %1; cvt.u32.u64 %0, t; }" : "=r"(a) : "l"(p));
    return a;
}
__device__ __forceinline__ uint32_t packh(float a, float b) {
    __half2 t = __floats2half2_rn(a, b);   // x=a (low), y=b (high)
    return *(uint32_t*)&t;
}
__device__ __forceinline__ void mma16(float* c, const uint32_t* a, const uint32_t* b) {
    asm volatile("mma.sync.aligned.m16n8k16.row.col.f32.f16.f16.f32 "
                 "{%0,%1,%2,%3}, {%4,%5,%6,%7}, {%8,%9}, {%0,%1,%2,%3};"
                 : "+f"(c[0]), "+f"(c[1]), "+f"(c[2]), "+f"(c[3])
                 : "r"(a[0]), "r"(a[1]), "r"(a[2]), "r"(a[3]), "r"(b[0]), "r"(b[1]));
}
// merge candidate (v,id) into triple (b1,i1,b2); first-index tie-break
__device__ __forceinline__ void merge3(float& b1, int& i1, float& b2, float v, int id) {
    if (v < b1 || (v == b1 && id < i1)) { b2 = b1; b1 = v; i1 = id; }
    else if (v < b2) b2 = v;
}
#define CP16(dst, src) \
    asm volatile("cp.async.cg.shared.global [%0], [%1], 16;" :: "r"(dst), "l"(src) : "memory")
#define CP_COMMIT() asm volatile("cp.async.commit_group;" ::: "memory")
#define CP_WAIT1()  asm volatile("cp.async.wait_group 1;" ::: "memory")
#define CP_WAIT0()  asm volatile("cp.async.wait_group 0;" ::: "memory")

// ---------------- fused prep: zero + cnorm + fp16 cb fragments ----------------
__global__ void __launch_bounds__(128) prep_all_kernel(const float* __restrict__ cb) {
    const int k = blockIdx.x, d = threadIdx.x;
    float v = cb[k * D_DIM + d];

    g_dw[k * D_DIM + d] = 0.f;
    if (d == 0) g_counts[k] = 0.f;
    if (k == 0 && d == 0) { g_loss = 0.f; g_fixcnt = 0; }

    float vn = __shfl_xor_sync(0xffffffffu, v, 1);

    float sq = v * v;
    #pragma unroll
    for (int o = 16; o; o >>= 1) sq += __shfl_xor_sync(0xffffffffu, sq, o);
    __shared__ float ws[4];
    if ((d & 31) == 0) ws[d >> 5] = sq;
    __syncthreads();
    if (d == 0) g_cnorm[k] = ws[0] + ws[1] + ws[2] + ws[3];

    if ((d & 1) == 0) {
        uint32_t ph = packh(v, vn);
        int tile = k >> 6, c = k & 63;
        int nf = c >> 3, np = nf >> 1, nin = c & 7;
        int s  = d >> 4, dk = d & 15;
        int kb = dk >> 3, lq = (dk & 7) >> 1;
        int lane = nin * 4 + lq;
        int comp = (nf & 1) * 2 + kb;
        g_Bh[(((tile * 8 + s) * 4 + np) * 32 + lane) * 4 + comp] = ph;
    }
}

// ---------------- z -> fp16, mma-fragment-packed ----------------
#define ZT_STRIDE 132
__global__ void __launch_bounds__(256) prep_z_kernel(const float* __restrict__ z) {
    extern __shared__ float zt[];                     // [128 d][ZT_STRIDE]
    const int tid  = threadIdx.x;
    const int ctaM = blockIdx.x;
    const int b  = ctaM >> 3;
    const int s0 = (ctaM & 7) << 7;
    const float* zp = z + (size_t)b * 131072 + s0;

    #pragma unroll
    for (int j = 0; j < 16; j++) {
        int u  = j * 256 + tid;
        int d  = u >> 5, t4 = (u & 31) << 2;
        float4 v = *(const float4*)&zp[(size_t)d * 1024 + t4];
        *(float4*)&zt[d * ZT_STRIDE + t4] = v;
    }
    __syncthreads();

    #pragma unroll
    for (int j = 0; j < 8; j++) {
        int u = j * 256 + tid;
        int f = u >> 8, s = (u >> 5) & 7, l = u & 31;
        int T0 = f * 16 + (l >> 2);
        int c0 = s * 16 + (l & 3) * 2;
        uint32_t rh[4];
        rh[0] = packh(zt[(c0    ) * ZT_STRIDE + T0],     zt[(c0 + 1) * ZT_STRIDE + T0]);
        rh[1] = packh(zt[(c0    ) * ZT_STRIDE + T0 + 8], zt[(c0 + 1) * ZT_STRIDE + T0 + 8]);
        rh[2] = packh(zt[(c0 + 8) * ZT_STRIDE + T0],     zt[(c0 + 9) * ZT_STRIDE + T0]);
        rh[3] = packh(zt[(c0 + 8) * ZT_STRIDE + T0 + 8], zt[(c0 + 9) * ZT_STRIDE + T0 + 8]);
        g_Ah[ctaM * 2048 + u] = make_uint4(rh[0], rh[1], rh[2], rh[3]);
    }
}

// ---------------- fp16 screening GEMM + argmin (best + 2nd best) ----------------
__global__ void __launch_bounds__(256, 2) argmin_mma_kernel() {
    extern __shared__ char smem[];
    const uint32_t smb = smem_u32(smem);
    const int tid = threadIdx.x;
    const int l   = tid & 31, w = tid >> 5;
    const int wr  = w & 3,    wc = w >> 2;
    const int lq  = l & 3,    lr = l >> 2;
    const int ctaM = blockIdx.x;

    {
        const uint4* gAh = g_Ah + (size_t)ctaM * 2048;
        #pragma unroll
        for (int j = 0; j < 8; j++) {
            int c = j * 256 + tid;
            CP16(smb + SM_A + c * 16, gAh + c);
        }
        CP16(smb + SM_CN + tid * 16, g_cnorm + tid * 4);
        CP_COMMIT();
    }
    {
        const uint4* bh = (const uint4*)g_Bh;
        #pragma unroll
        for (int j = 0; j < 4; j++) {
            int c = j * 256 + tid;
            CP16(smb + SM_B + c * 16, bh + c);
        }
        CP_COMMIT();
    }

    float acc[2][4][4];
    float best [2][2] = {{3.4e38f, 3.4e38f}, {3.4e38f, 3.4e38f}};
    float best2[2][2] = {{3.4e38f, 3.4e38f}, {3.4e38f, 3.4e38f}};
    int   bidx [2][2] = {{0, 0}, {0, 0}};

    for (int t = 0; t < 16; t++) {
        if (t < 15) {
            const uint4* bh = (const uint4*)g_Bh + (t + 1) * 1024;
            uint32_t dst = smb + SM_B + ((t + 1) & 1) * 16384;
            #pragma unroll
            for (int j = 0; j < 4; j++) {
                int c = j * 256 + tid;
                CP16(dst + c * 16, bh + c);
            }
            CP_COMMIT();
            CP_WAIT1();
        } else {
            CP_WAIT0();
        }
        __syncthreads();

        #pragma unroll
        for (int m = 0; m < 2; m++)
            #pragma unroll
            for (int n = 0; n < 4; n++)
                #pragma unroll
                for (int e = 0; e < 4; e++) acc[m][n][e] = 0.f;

        const uint4* Ah4 = (const uint4*)(smem + SM_A);
        const uint4* Bh4 = (const uint4*)(smem + SM_B + (size_t)(t & 1) * 16384);

        #pragma unroll
        for (int s = 0; s < 8; s++) {
            uint4 A0 = Ah4[((wr * 2 + 0) * 8 + s) * 32 + l];
            uint4 A1 = Ah4[((wr * 2 + 1) * 8 + s) * 32 + l];
            uint4 B0 = Bh4[(s * 4 + wc * 2 + 0) * 32 + l];
            uint4 B1 = Bh4[(s * 4 + wc * 2 + 1) * 32 + l];

            uint32_t ah[2][4] = {{A0.x, A0.y, A0.z, A0.w}, {A1.x, A1.y, A1.z, A1.w}};
            uint32_t bh[4][2] = {{B0.x, B0.y}, {B0.z, B0.w}, {B1.x, B1.y}, {B1.z, B1.w}};

            #pragma unroll
            for (int m = 0; m < 2; m++)
                #pragma unroll
                for (int n = 0; n < 4; n++) mma16(acc[m][n], ah[m], bh[n]);
        }

        const float* cn = (const float*)(smem + SM_CN);
        #pragma unroll
        for (int m = 0; m < 2; m++)
            #pragma unroll
            for (int n = 0; n < 4; n++)
                #pragma unroll
                for (int e = 0; e < 4; e++) {
                    int code = t * 64 + (wc * 4 + n) * 8 + lq * 2 + (e & 1);
                    float dist = fmaf(-2.f, acc[m][n][e], cn[code]);
                    int rb = e >> 1;
                    merge3(best[m][rb], bidx[m][rb], best2[m][rb], dist, code);
                }
        __syncthreads();
    }

    float* redv = (float*)(smem + SM_REDV);
    int*   redi = (int*)(smem + SM_REDI);
    float* red2 = (float*)(smem + SM_RED2);
    #pragma unroll
    for (int m = 0; m < 2; m++)
        #pragma unroll
        for (int rb = 0; rb < 2; rb++) {
            float v1 = best[m][rb], v2 = best2[m][rb];
            int   id = bidx[m][rb];
            #pragma unroll
            for (int off = 1; off <= 2; off <<= 1) {
                float ov1 = __shfl_xor_sync(0xffffffffu, v1, off);
                float ov2 = __shfl_xor_sync(0xffffffffu, v2, off);
                int   oi  = __shfl_xor_sync(0xffffffffu, id, off);
                merge3(v1, id, v2, ov1, oi);
                merge3(v1, id, v2, ov2, 0x7fffffff);
            }
            if (lq == 0) {
                int row = wr * 32 + m * 16 + rb * 8 + lr;
                redv[wc * 128 + row] = v1;
                redi[wc * 128 + row] = id;
                red2[wc * 128 + row] = v2;
            }
        }
    __syncthreads();
    if (tid < 128) {
        float v1 = redv[tid],       s1 = red2[tid];
        float w1 = redv[128 + tid], w2 = red2[128 + tid];
        int   i1 = redi[tid],       j1 = redi[128 + tid];
        merge3(v1, i1, s1, w1, j1);
        merge3(v1, i1, s1, w2, 0x7fffffff);
        int token = ctaM * 128 + tid;
        g_idx[token] = i1;
        if (s1 - v1 < EPS_FLAG) {
            int p = atomicAdd(&g_fixcnt, 1);
            g_fixlist[p] = token;
        }
    }
}

// ---------------- exact fp32 recompute, tile-batched, float4-vectorized ----------------
#define FIX_G 16
#define CB_STR 132
__global__ void __launch_bounds__(256) fixup_kernel(const float* __restrict__ z,
                                                    const float* __restrict__ cb) {
    __shared__ float ztok[FIX_G][D_DIM];
    __shared__ float cbt[64 * CB_STR];
    __shared__ float cnt_[64];
    const int tid = threadIdx.x;
    const int tk = tid >> 4, cs = tid & 15;
    int cnt = g_fixcnt;
    int nIter = (cnt + FIX_G - 1) / FIX_G;

    for (int it = blockIdx.x; it < nIter; it += gridDim.x) {
        int base = it * FIX_G;
        for (int u = tid; u < FIX_G * D_DIM; u += 256) {
            int tt = u >> 7, d = u & 127;
            float v = 0.f;
            int ti = base + tt;
            if (ti < cnt) {
                int token = g_fixlist[ti];
                int b = token >> 10, s = token & 1023;
                v = z[(size_t)b * 131072 + (size_t)d * 1024 + s];
            }
            ztok[tt][d] = v;
        }

        float bv = 3.4e38f;
        int   bi = 0;
        for (int tile = 0; tile < 16; tile++) {
            __syncthreads();
            for (int u = tid; u < 2048; u += 256) {
                float4 vv = ((const float4*)cb)[tile * 2048 + u];
                *(float4*)&cbt[(u >> 5) * CB_STR + (u & 31) * 4] = vv;
            }
            if (tid < 64) cnt_[tid] = g_cnorm[tile * 64 + tid];
            __syncthreads();

            // vectorized: 1 zp LDS.128 + 4 cbt LDS.128 per 16 FMA
            float dot[4] = {0.f, 0.f, 0.f, 0.f};
            const float4* zp4 = (const float4*)ztok[tk];
            #pragma unroll 4
            for (int q4 = 0; q4 < 32; q4++) {
                float4 zv = zp4[q4];
                #pragma unroll
                for (int j = 0; j < 4; j++) {
                    float4 cv = *(const float4*)&cbt[(cs + j * 16) * CB_STR + q4 * 4];
                    dot[j] = fmaf(zv.x, cv.x, dot[j]);
                    dot[j] = fmaf(zv.y, cv.y, dot[j]);
                    dot[j] = fmaf(zv.z, cv.z, dot[j]);
                    dot[j] = fmaf(zv.w, cv.w, dot[j]);
                }
            }
            #pragma unroll
            for (int j = 0; j < 4; j++) {
                int c = cs + j * 16;
                float dist = fmaf(-2.f, dot[j], cnt_[c]);
                int code = tile * 64 + c;
                if (dist < bv || (dist == bv && code < bi)) { bv = dist; bi = code; }
            }
        }
        #pragma unroll
        for (int off = 1; off < 16; off <<= 1) {
            float ov = __shfl_xor_sync(0xffffffffu, bv, off);
            int   oi = __shfl_xor_sync(0xffffffffu, bi, off);
            if (ov < bv || (ov == bv && oi < bi)) { bv = ov; bi = oi; }
        }
        if (cs == 0 && base + tk < cnt) g_idx[g_fixlist[base + tk]] = bi;
        __syncthreads();
    }
}

// ---------------- gather quantized + loss + counts + idx (2 tokens/warp) ----------------
__global__ void __launch_bounds__(256) quant_kernel(const float* __restrict__ z,
                                                    const float* __restrict__ cb,
                                                    float* __restrict__ out) {
    int wid  = threadIdx.x >> 5;
    int lane = threadIdx.x & 31;
    int n0   = blockIdx.x * 16 + wid * 2;

    int k0 = g_idx[n0];
    int k1 = g_idx[n0 + 1];

    float4 q0 = *(const float4*)&cb[k0 * D_DIM + lane * 4];
    float4 q1 = *(const float4*)&cb[k1 * D_DIM + lane * 4];
    size_t o0 = (size_t)n0 * D_DIM + lane * 4;
    float4 z0 = *(const float4*)&z[o0];
    float4 z1 = *(const float4*)&z[o0 + D_DIM];
    *(float4*)&out[Q_OFF + o0]         = q0;
    *(float4*)&out[Q_OFF + o0 + D_DIM] = q1;

    float dx = q0.x - z0.x, dy = q0.y - z0.y, dz = q0.z - z0.z, dw = q0.w - z0.w;
    float s  = dx * dx + dy * dy + dz * dz + dw * dw;
    dx = q1.x - z1.x; dy = q1.y - z1.y; dz = q1.z - z1.z; dw = q1.w - z1.w;
    s += dx * dx + dy * dy + dz * dz + dw * dw;
    #pragma unroll
    for (int o = 16; o; o >>= 1) s += __shfl_xor_sync(0xffffffffu, s, o);

    __shared__ float ws[8];
    if (lane == 0) {
        ws[wid] = s;
        atomicAdd(&g_counts[k0], 1.f);
        atomicAdd(&g_counts[k1], 1.f);
        out[IDX_OFF + n0]     = (float)k0;
        out[IDX_OFF + n0 + 1] = (float)k1;
    }
    __syncthreads();
    if (threadIdx.x == 0) {
        float t = 0.f;
        #pragma unroll
        for (int i = 0; i < 8; i++) t += ws[i];
        atomicAdd(&g_loss, t);
    }
}

// ---------------- dw scatter: vector red.v4 (4 d per thread) ----------------
__global__ void __launch_bounds__(256) dw_kernel(const float* __restrict__ z) {
    int u  = blockIdx.x * blockDim.x + threadIdx.x;   // < 2097152
    int s  = u & 1023;
    int dg = (u >> 10) & 31;
    int b  = u >> 15;
    int n  = (b << 10) + s;
    int k  = g_idx[n];
    const float* zp = z + (size_t)b * 131072 + (size_t)dg * 4096 + s;
    float v0 = zp[0], v1 = zp[1024], v2 = zp[2048], v3 = zp[3072];
    float* dst = &g_dw[k * D_DIM + dg * 4];
    asm volatile("red.global.add.v4.f32 [%0], {%1,%2,%3,%4};"
                 :: "l"(dst), "f"(v0), "f"(v1), "f"(v2), "f"(v3) : "memory");
}

// ---------------- EMA count update + weights + losses ----------------
__global__ void finalize1_kernel(const float* __restrict__ ema_count,
                                 float* __restrict__ out) {
    int k = threadIdx.x;
    float c = EMA * ema_count[k] + (1.f - EMA) * g_counts[k];
    out[CNT_OFF + k] = c;

    __shared__ float sm[1024];
    sm[k] = c;
    __syncthreads();
    for (int o = 512; o; o >>= 1) {
        if (k < o) sm[k] += sm[k + o];
        __syncthreads();
    }
    float n = sm[0];
    g_weights[k] = (c + EPSV) / (n + K_CODES * EPSV) * n;

    if (k == 0) {
        float L = g_loss / 8388608.f;
        out[L_OFF]     = L;
        out[L_OFF + 1] = L;
    }
}

// ---------------- EMA weight update + new codebook ----------------
__global__ void finalize2_kernel(const float* __restrict__ ema_weight,
                                 float* __restrict__ out) {
    int i = blockIdx.x * blockDim.x + threadIdx.x;
    int k = i >> 7;
    float w = EMA * ema_weight[i] + (1.f - EMA) * g_dw[i];
    out[EMW_OFF + i] = w;
    out[CB_OFF + i]  = w / g_weights[k];
}

// ---------------- launch ----------------
extern "C" void kernel_launch(void* const* d_in, const int* in_sizes, int n_in,
                              void* d_out, int out_size) {
    const float* z          = (const float*)d_in[0];
    const float* cb         = (const float*)d_in[1];
    const float* ema_count  = (const float*)d_in[2];
    const float* ema_weight = (const float*)d_in[3];
    float* out = (float*)d_out;

    cudaFuncSetAttribute(argmin_mma_kernel,
                         cudaFuncAttributeMaxDynamicSharedMemorySize, SM_TOTAL);
    cudaFuncSetAttribute(prep_z_kernel,
                         cudaFuncAttributeMaxDynamicSharedMemorySize, 128 * ZT_STRIDE * 4);

    prep_all_kernel<<<K_CODES, 128>>>(cb);
    prep_z_kernel<<<N_TOK / 128, 256, 128 * ZT_STRIDE * 4>>>(z);
    argmin_mma_kernel<<<N_TOK / 128, 256, SM_TOTAL>>>();
    fixup_kernel<<<256, 256>>>(z, cb);
    quant_kernel<<<N_TOK / 16, 256>>>(z, cb, out);
    dw_kernel<<<Z_ELEMS / 1024, 256>>>(z);
    finalize1_kernel<<<1, 1024>>>(ema_count, out);
    finalize2_kernel<<<512, 256>>>(ema_weight, out);
}

// round 10
// speedup vs baseline: 1.4393x; 1.0280x over previous
#include <cuda_runtime.h>
#include <cuda_fp16.h>
#include <cstdint>

// ---------------- problem constants ----------------
#define K_CODES   1024
#define D_DIM     128
#define N_TOK     65536        // 64 * 32 * 32 tokens (BHWC order)
#define Z_ELEMS   8388608      // 64 * 128 * 32 * 32
#define EMA       0.99f
#define EPSV      1e-5f
#define EPS_FLAG  0.15f        // approx-gap threshold for exact recompute (7.8 sigma)

// ---------------- output layout (flattened reference tuple, fp32) ----------------
#define Q_OFF     0
#define IDX_OFF   8388608
#define L_OFF     8454144
#define CB_OFF    8454146
#define CNT_OFF   8585218
#define EMW_OFF   8586242

// ---------------- smem layout for argmin (bytes) ----------------
#define SM_A      0            // 32KB: A fp16 frag-packed
#define SM_B      32768        // 2 stages * 16KB
#define SM_CN     65536        // 1024 floats
#define SM_REDV   69632        // 256 floats (best)
#define SM_REDI   70656        // 256 ints  (best idx)
#define SM_RED2   71680        // 256 floats (second best)
#define SM_TOTAL  72704

// ---------------- global scratch ----------------
__device__ uint4    g_Ah[512 * 2048];     // z fp16, frag-packed [cta][f8][s8][lane32] (16.7MB)
__device__ uint32_t g_Bh[65536];          // cb fp16 [tile16][s8][np4][lane32][comp4] (256KB)
__device__ float    g_cnorm[K_CODES];
__device__ float    g_counts[K_CODES];
__device__ float    g_dw[K_CODES * D_DIM];
__device__ int      g_idx[N_TOK];
__device__ float    g_loss;
__device__ float    g_weights[K_CODES];
__device__ int      g_fixcnt;
__device__ int      g_fixlist[N_TOK];
__device__ unsigned long long g_fixkey[N_TOK];   // (ordered-dist << 32) | code

// ---------------- helpers ----------------
__device__ __forceinline__ uint32_t smem_u32(const void* p) {
    uint32_t a;
    asm("{ .reg .u64 t; cvta.to.shared.u64 t, %1; cvt.u32.u64 %0, t; }" : "=r"(a) : "l"(p));
    return a;
}
__device__ __forceinline__ uint32_t packh(float a, float b) {
    __half2 t = __floats2half2_rn(a, b);   // x=a (low), y=b (high)
    return *(uint32_t*)&t;
}
__device__ __forceinline__ void mma16(float* c, const uint32_t* a, const uint32_t* b) {
    asm volatile("mma.sync.aligned.m16n8k16.row.col.f32.f16.f16.f32 "
                 "{%0,%1,%2,%3}, {%4,%5,%6,%7}, {%8,%9}, {%0,%1,%2,%3};"
                 : "+f"(c[0]), "+f"(c[1]), "+f"(c[2]), "+f"(c[3])
                 : "r"(a[0]), "r"(a[1]), "r"(a[2]), "r"(a[3]), "r"(b[0]), "r"(b[1]));
}
// merge candidate (v,id) into triple (b1,i1,b2); first-index tie-break
__device__ __forceinline__ void merge3(float& b1, int& i1, float& b2, float v, int id) {
    if (v < b1 || (v == b1 && id < i1)) { b2 = b1; b1 = v; i1 = id; }
    else if (v < b2) b2 = v;
}
// order-preserving float -> uint32 (monotone for all finite values)
__device__ __forceinline__ uint32_t fkey(float f) {
    uint32_t b = __float_as_uint(f);
    return (b & 0x80000000u) ? ~b : (b | 0x80000000u);
}
#define CP16(dst, src) \
    asm volatile("cp.async.cg.shared.global [%0], [%1], 16;" :: "r"(dst), "l"(src) : "memory")
#define CP_COMMIT() asm volatile("cp.async.commit_group;" ::: "memory")
#define CP_WAIT1()  asm volatile("cp.async.wait_group 1;" ::: "memory")
#define CP_WAIT0()  asm volatile("cp.async.wait_group 0;" ::: "memory")

// ---------------- fused prep: zero + cnorm + fp16 cb fragments ----------------
__global__ void __launch_bounds__(128) prep_all_kernel(const float* __restrict__ cb) {
    const int k = blockIdx.x, d = threadIdx.x;
    float v = cb[k * D_DIM + d];

    g_dw[k * D_DIM + d] = 0.f;
    if (d == 0) g_counts[k] = 0.f;
    if (k == 0 && d == 0) { g_loss = 0.f; g_fixcnt = 0; }

    float vn = __shfl_xor_sync(0xffffffffu, v, 1);

    float sq = v * v;
    #pragma unroll
    for (int o = 16; o; o >>= 1) sq += __shfl_xor_sync(0xffffffffu, sq, o);
    __shared__ float ws[4];
    if ((d & 31) == 0) ws[d >> 5] = sq;
    __syncthreads();
    if (d == 0) g_cnorm[k] = ws[0] + ws[1] + ws[2] + ws[3];

    if ((d & 1) == 0) {
        uint32_t ph = packh(v, vn);
        int tile = k >> 6, c = k & 63;
        int nf = c >> 3, np = nf >> 1, nin = c & 7;
        int s  = d >> 4, dk = d & 15;
        int kb = dk >> 3, lq = (dk & 7) >> 1;
        int lane = nin * 4 + lq;
        int comp = (nf & 1) * 2 + kb;
        g_Bh[(((tile * 8 + s) * 4 + np) * 32 + lane) * 4 + comp] = ph;
    }
}

// ---------------- z -> fp16, mma-fragment-packed ----------------
#define ZT_STRIDE 132
__global__ void __launch_bounds__(256) prep_z_kernel(const float* __restrict__ z) {
    extern __shared__ float zt[];                     // [128 d][ZT_STRIDE]
    const int tid  = threadIdx.x;
    const int ctaM = blockIdx.x;
    const int b  = ctaM >> 3;
    const int s0 = (ctaM & 7) << 7;
    const float* zp = z + (size_t)b * 131072 + s0;

    #pragma unroll
    for (int j = 0; j < 16; j++) {
        int u  = j * 256 + tid;
        int d  = u >> 5, t4 = (u & 31) << 2;
        float4 v = *(const float4*)&zp[(size_t)d * 1024 + t4];
        *(float4*)&zt[d * ZT_STRIDE + t4] = v;
    }
    __syncthreads();

    #pragma unroll
    for (int j = 0; j < 8; j++) {
        int u = j * 256 + tid;
        int f = u >> 8, s = (u >> 5) & 7, l = u & 31;
        int T0 = f * 16 + (l >> 2);
        int c0 = s * 16 + (l & 3) * 2;
        uint32_t rh[4];
        rh[0] = packh(zt[(c0    ) * ZT_STRIDE + T0],     zt[(c0 + 1) * ZT_STRIDE + T0]);
        rh[1] = packh(zt[(c0    ) * ZT_STRIDE + T0 + 8], zt[(c0 + 1) * ZT_STRIDE + T0 + 8]);
        rh[2] = packh(zt[(c0 + 8) * ZT_STRIDE + T0],     zt[(c0 + 9) * ZT_STRIDE + T0]);
        rh[3] = packh(zt[(c0 + 8) * ZT_STRIDE + T0 + 8], zt[(c0 + 9) * ZT_STRIDE + T0 + 8]);
        g_Ah[ctaM * 2048 + u] = make_uint4(rh[0], rh[1], rh[2], rh[3]);
    }
}

// ---------------- fp16 screening GEMM + argmin (best + 2nd best) ----------------
__global__ void __launch_bounds__(256, 2) argmin_mma_kernel() {
    extern __shared__ char smem[];
    const uint32_t smb = smem_u32(smem);
    const int tid = threadIdx.x;
    const int l   = tid & 31, w = tid >> 5;
    const int wr  = w & 3,    wc = w >> 2;
    const int lq  = l & 3,    lr = l >> 2;
    const int ctaM = blockIdx.x;

    {
        const uint4* gAh = g_Ah + (size_t)ctaM * 2048;
        #pragma unroll
        for (int j = 0; j < 8; j++) {
            int c = j * 256 + tid;
            CP16(smb + SM_A + c * 16, gAh + c);
        }
        CP16(smb + SM_CN + tid * 16, g_cnorm + tid * 4);
        CP_COMMIT();
    }
    {
        const uint4* bh = (const uint4*)g_Bh;
        #pragma unroll
        for (int j = 0; j < 4; j++) {
            int c = j * 256 + tid;
            CP16(smb + SM_B + c * 16, bh + c);
        }
        CP_COMMIT();
    }

    float acc[2][4][4];
    float best [2][2] = {{3.4e38f, 3.4e38f}, {3.4e38f, 3.4e38f}};
    float best2[2][2] = {{3.4e38f, 3.4e38f}, {3.4e38f, 3.4e38f}};
    int   bidx [2][2] = {{0, 0}, {0, 0}};

    for (int t = 0; t < 16; t++) {
        if (t < 15) {
            const uint4* bh = (const uint4*)g_Bh + (t + 1) * 1024;
            uint32_t dst = smb + SM_B + ((t + 1) & 1) * 16384;
            #pragma unroll
            for (int j = 0; j < 4; j++) {
                int c = j * 256 + tid;
                CP16(dst + c * 16, bh + c);
            }
            CP_COMMIT();
            CP_WAIT1();
        } else {
            CP_WAIT0();
        }
        __syncthreads();

        #pragma unroll
        for (int m = 0; m < 2; m++)
            #pragma unroll
            for (int n = 0; n < 4; n++)
                #pragma unroll
                for (int e = 0; e < 4; e++) acc[m][n][e] = 0.f;

        const uint4* Ah4 = (const uint4*)(smem + SM_A);
        const uint4* Bh4 = (const uint4*)(smem + SM_B + (size_t)(t & 1) * 16384);

        #pragma unroll
        for (int s = 0; s < 8; s++) {
            uint4 A0 = Ah4[((wr * 2 + 0) * 8 + s) * 32 + l];
            uint4 A1 = Ah4[((wr * 2 + 1) * 8 + s) * 32 + l];
            uint4 B0 = Bh4[(s * 4 + wc * 2 + 0) * 32 + l];
            uint4 B1 = Bh4[(s * 4 + wc * 2 + 1) * 32 + l];

            uint32_t ah[2][4] = {{A0.x, A0.y, A0.z, A0.w}, {A1.x, A1.y, A1.z, A1.w}};
            uint32_t bh[4][2] = {{B0.x, B0.y}, {B0.z, B0.w}, {B1.x, B1.y}, {B1.z, B1.w}};

            #pragma unroll
            for (int m = 0; m < 2; m++)
                #pragma unroll
                for (int n = 0; n < 4; n++) mma16(acc[m][n], ah[m], bh[n]);
        }

        const float* cn = (const float*)(smem + SM_CN);
        #pragma unroll
        for (int m = 0; m < 2; m++)
            #pragma unroll
            for (int n = 0; n < 4; n++)
                #pragma unroll
                for (int e = 0; e < 4; e++) {
                    int code = t * 64 + (wc * 4 + n) * 8 + lq * 2 + (e & 1);
                    float dist = fmaf(-2.f, acc[m][n][e], cn[code]);
                    int rb = e >> 1;
                    merge3(best[m][rb], bidx[m][rb], best2[m][rb], dist, code);
                }
        __syncthreads();
    }

    float* redv = (float*)(smem + SM_REDV);
    int*   redi = (int*)(smem + SM_REDI);
    float* red2 = (float*)(smem + SM_RED2);
    #pragma unroll
    for (int m = 0; m < 2; m++)
        #pragma unroll
        for (int rb = 0; rb < 2; rb++) {
            float v1 = best[m][rb], v2 = best2[m][rb];
            int   id = bidx[m][rb];
            #pragma unroll
            for (int off = 1; off <= 2; off <<= 1) {
                float ov1 = __shfl_xor_sync(0xffffffffu, v1, off);
                float ov2 = __shfl_xor_sync(0xffffffffu, v2, off);
                int   oi  = __shfl_xor_sync(0xffffffffu, id, off);
                merge3(v1, id, v2, ov1, oi);
                merge3(v1, id, v2, ov2, 0x7fffffff);
            }
            if (lq == 0) {
                int row = wr * 32 + m * 16 + rb * 8 + lr;
                redv[wc * 128 + row] = v1;
                redi[wc * 128 + row] = id;
                red2[wc * 128 + row] = v2;
            }
        }
    __syncthreads();
    if (tid < 128) {
        float v1 = redv[tid],       s1 = red2[tid];
        float w1 = redv[128 + tid], w2 = red2[128 + tid];
        int   i1 = redi[tid],       j1 = redi[128 + tid];
        merge3(v1, i1, s1, w1, j1);
        merge3(v1, i1, s1, w2, 0x7fffffff);
        int token = ctaM * 128 + tid;
        g_idx[token] = i1;
        if (s1 - v1 < EPS_FLAG) {
            g_fixkey[token] = 0xFFFFFFFFFFFFFFFFull;
            int p = atomicAdd(&g_fixcnt, 1);
            g_fixlist[p] = token;
        }
    }
}

// ---------------- exact fp32 recompute, 2D (token-batch x code-tile) ----------------
// One block = 16 tokens x one 64-code tile. Cross-block merge via u64 atomicMin.
#define FIX_G 16
#define CB_STR 132
__global__ void __launch_bounds__(256) fixup_kernel(const float* __restrict__ z,
                                                    const float* __restrict__ cb) {
    __shared__ float ztok[FIX_G][D_DIM];
    __shared__ float cbt[64 * CB_STR];
    __shared__ float cnt_[64];
    const int tid = threadIdx.x;
    const int tk = tid >> 4, cs = tid & 15;
    const int cnt = g_fixcnt;
    const int nwork = ((cnt + FIX_G - 1) / FIX_G) * 16;   // batches * 16 tiles

    for (int wi = blockIdx.x; wi < nwork; wi += gridDim.x) {
        int batch = wi >> 4, tile = wi & 15;
        int base = batch * FIX_G;

        // load 16 token z rows (gathered)
        for (int u = tid; u < FIX_G * D_DIM; u += 256) {
            int tt = u >> 7, d = u & 127;
            float v = 0.f;
            int ti = base + tt;
            if (ti < cnt) {
                int token = g_fixlist[ti];
                int b = token >> 10, s = token & 1023;
                v = z[(size_t)b * 131072 + (size_t)d * 1024 + s];
            }
            ztok[tt][d] = v;
        }
        // load this code tile (32KB) + its norms
        for (int u = tid; u < 2048; u += 256) {
            float4 vv = ((const float4*)cb)[tile * 2048 + u];
            *(float4*)&cbt[(u >> 5) * CB_STR + (u & 31) * 4] = vv;
        }
        if (tid < 64) cnt_[tid] = g_cnorm[tile * 64 + tid];
        __syncthreads();

        // each thread: 4 codes x 128 d
        float dot[4] = {0.f, 0.f, 0.f, 0.f};
        const float4* zp4 = (const float4*)ztok[tk];
        #pragma unroll 4
        for (int q4 = 0; q4 < 32; q4++) {
            float4 zv = zp4[q4];
            #pragma unroll
            for (int j = 0; j < 4; j++) {
                float4 cv = *(const float4*)&cbt[(cs + j * 16) * CB_STR + q4 * 4];
                dot[j] = fmaf(zv.x, cv.x, dot[j]);
                dot[j] = fmaf(zv.y, cv.y, dot[j]);
                dot[j] = fmaf(zv.z, cv.z, dot[j]);
                dot[j] = fmaf(zv.w, cv.w, dot[j]);
            }
        }
        // local best (ascending code -> first-index tie-break), then u64 key
        unsigned long long key = 0xFFFFFFFFFFFFFFFFull;
        #pragma unroll
        for (int j = 0; j < 4; j++) {
            int c = cs + j * 16;
            float dist = fmaf(-2.f, dot[j], cnt_[c]);
            unsigned long long k2 =
                ((unsigned long long)fkey(dist) << 32) | (unsigned)(tile * 64 + c);
            if (k2 < key) key = k2;
        }
        // reduce over the 16 lanes of this token (contiguous half-warp)
        #pragma unroll
        for (int off = 1; off < 16; off <<= 1) {
            unsigned long long ok = __shfl_xor_sync(0xffffffffu, key, off);
            if (ok < key) key = ok;
        }
        if (cs == 0 && base + tk < cnt)
            atomicMin(&g_fixkey[g_fixlist[base + tk]], key);
        __syncthreads();
    }
}

// ---------------- writeback: key -> g_idx ----------------
__global__ void __launch_bounds__(256) fixwb_kernel() {
    int cnt = g_fixcnt;
    for (int i = blockIdx.x * blockDim.x + threadIdx.x; i < cnt;
         i += gridDim.x * blockDim.x) {
        int token = g_fixlist[i];
        g_idx[token] = (int)(g_fixkey[token] & 1023u);
    }
}

// ---------------- gather quantized + loss + counts + idx (2 tokens/warp) ----------------
__global__ void __launch_bounds__(256) quant_kernel(const float* __restrict__ z,
                                                    const float* __restrict__ cb,
                                                    float* __restrict__ out) {
    int wid  = threadIdx.x >> 5;
    int lane = threadIdx.x & 31;
    int n0   = blockIdx.x * 16 + wid * 2;

    int k0 = g_idx[n0];
    int k1 = g_idx[n0 + 1];

    float4 q0 = *(const float4*)&cb[k0 * D_DIM + lane * 4];
    float4 q1 = *(const float4*)&cb[k1 * D_DIM + lane * 4];
    size_t o0 = (size_t)n0 * D_DIM + lane * 4;
    float4 z0 = *(const float4*)&z[o0];
    float4 z1 = *(const float4*)&z[o0 + D_DIM];
    *(float4*)&out[Q_OFF + o0]         = q0;
    *(float4*)&out[Q_OFF + o0 + D_DIM] = q1;

    float dx = q0.x - z0.x, dy = q0.y - z0.y, dz = q0.z - z0.z, dw = q0.w - z0.w;
    float s  = dx * dx + dy * dy + dz * dz + dw * dw;
    dx = q1.x - z1.x; dy = q1.y - z1.y; dz = q1.z - z1.z; dw = q1.w - z1.w;
    s += dx * dx + dy * dy + dz * dz + dw * dw;
    #pragma unroll
    for (int o = 16; o; o >>= 1) s += __shfl_xor_sync(0xffffffffu, s, o);

    __shared__ float ws[8];
    if (lane == 0) {
        ws[wid] = s;
        atomicAdd(&g_counts[k0], 1.f);
        atomicAdd(&g_counts[k1], 1.f);
        out[IDX_OFF + n0]     = (float)k0;
        out[IDX_OFF + n0 + 1] = (float)k1;
    }
    __syncthreads();
    if (threadIdx.x == 0) {
        float t = 0.f;
        #pragma unroll
        for (int i = 0; i < 8; i++) t += ws[i];
        atomicAdd(&g_loss, t);
    }
}

// ---------------- dw scatter: vector red.v4 (4 d per thread) ----------------
__global__ void __launch_bounds__(256) dw_kernel(const float* __restrict__ z) {
    int u  = blockIdx.x * blockDim.x + threadIdx.x;   // < 2097152
    int s  = u & 1023;
    int dg = (u >> 10) & 31;
    int b  = u >> 15;
    int n  = (b << 10) + s;
    int k  = g_idx[n];
    const float* zp = z + (size_t)b * 131072 + (size_t)dg * 4096 + s;
    float v0 = zp[0], v1 = zp[1024], v2 = zp[2048], v3 = zp[3072];
    float* dst = &g_dw[k * D_DIM + dg * 4];
    asm volatile("red.global.add.v4.f32 [%0], {%1,%2,%3,%4};"
                 :: "l"(dst), "f"(v0), "f"(v1), "f"(v2), "f"(v3) : "memory");
}

// ---------------- EMA count update + weights + losses ----------------
__global__ void finalize1_kernel(const float* __restrict__ ema_count,
                                 float* __restrict__ out) {
    int k = threadIdx.x;
    float c = EMA * ema_count[k] + (1.f - EMA) * g_counts[k];
    out[CNT_OFF + k] = c;

    __shared__ float sm[1024];
    sm[k] = c;
    __syncthreads();
    for (int o = 512; o; o >>= 1) {
        if (k < o) sm[k] += sm[k + o];
        __syncthreads();
    }
    float n = sm[0];
    g_weights[k] = (c + EPSV) / (n + K_CODES * EPSV) * n;

    if (k == 0) {
        float L = g_loss / 8388608.f;
        out[L_OFF]     = L;
        out[L_OFF + 1] = L;
    }
}

// ---------------- EMA weight update + new codebook ----------------
__global__ void finalize2_kernel(const float* __restrict__ ema_weight,
                                 float* __restrict__ out) {
    int i = blockIdx.x * blockDim.x + threadIdx.x;
    int k = i >> 7;
    float w = EMA * ema_weight[i] + (1.f - EMA) * g_dw[i];
    out[EMW_OFF + i] = w;
    out[CB_OFF + i]  = w / g_weights[k];
}

// ---------------- launch ----------------
extern "C" void kernel_launch(void* const* d_in, const int* in_sizes, int n_in,
                              void* d_out, int out_size) {
    const float* z          = (const float*)d_in[0];
    const float* cb         = (const float*)d_in[1];
    const float* ema_count  = (const float*)d_in[2];
    const float* ema_weight = (const float*)d_in[3];
    float* out = (float*)d_out;

    cudaFuncSetAttribute(argmin_mma_kernel,
                         cudaFuncAttributeMaxDynamicSharedMemorySize, SM_TOTAL);
    cudaFuncSetAttribute(prep_z_kernel,
                         cudaFuncAttributeMaxDynamicSharedMemorySize, 128 * ZT_STRIDE * 4);

    prep_all_kernel<<<K_CODES, 128>>>(cb);
    prep_z_kernel<<<N_TOK / 128, 256, 128 * ZT_STRIDE * 4>>>(z);
    argmin_mma_kernel<<<N_TOK / 128, 256, SM_TOTAL>>>();
    fixup_kernel<<<1024, 256>>>(z, cb);
    fixwb_kernel<<<64, 256>>>();
    quant_kernel<<<N_TOK / 16, 256>>>(z, cb, out);
    dw_kernel<<<Z_ELEMS / 1024, 256>>>(z);
    finalize1_kernel<<<1, 1024>>>(ema_count, out);
    finalize2_kernel<<<512, 256>>>(ema_weight, out);
}